// round 1
// baseline (speedup 1.0000x reference)
#include <cuda_runtime.h>
#include <cuda_bf16.h>
#include <math.h>

// ---------------------------------------------------------------------------
// Problem constants
// ---------------------------------------------------------------------------
#define BATCH 32
#define CCH   128           // channels / d_model
#define HH    110           // spatial
#define PIX   (HH*HH)       // 12100
#define KTOK  768
#define NHEAD 8
#define HD    16
#define NTOK  (BATCH*KTOK)  // 24576

// ---------------------------------------------------------------------------
// Scratch (static device globals; no allocation allowed)
// ---------------------------------------------------------------------------
__device__ float g_y[4][BATCH*PIX];          // conv partial sums (4 channel chunks)
__device__ float g_imp[BATCH*PIX];           // importance map
__device__ int   g_idx[BATCH*KTOK];          // selected (sorted) pixel indices
__device__ float g_freq[64];                 // positional-encoding frequencies
__device__ float g_tokens[NTOK*CCH];
__device__ float g_qkv[NTOK*3*CCH];
__device__ float g_attn[NTOK*CCH];
__device__ float g_t1[NTOK*CCH];
__device__ float g_h1[NTOK*2*CCH];
__device__ float g_tmp[NTOK*CCH];
__device__ float g_t2[NTOK*CCH];

// ---------------------------------------------------------------------------
// 1) Dilated conv (k=7, d=5, p=15), residue decomposition.
//    grid (4 cchunk, 4 rowchunk, 32 batch), block 160 (= 32 rows x 5 residues)
//    Each thread: one output row + one column residue -> 22 outputs.
// ---------------------------------------------------------------------------
__global__ void conv_kernel(const float* __restrict__ x, const float* __restrict__ w)
{
    __shared__ float tile[62][110];
    __shared__ float ws[49];

    const int cc  = blockIdx.x;
    const int rc  = blockIdx.y;
    const int b   = blockIdx.z;
    const int tid = threadIdx.x;

    const int r_local = tid / 5;
    const int res     = tid % 5;
    const int row0    = rc * 32;
    const int nrows   = min(32, HH - row0);
    const bool active = (r_local < nrows);

    float acc[22];
#pragma unroll
    for (int m = 0; m < 22; m++) acc[m] = 0.f;

    for (int ci = 0; ci < 32; ci++) {
        const int c = cc * 32 + ci;
        __syncthreads();
        if (tid < 49) ws[tid] = w[c * 49 + tid];
        const float* xp = x + ((size_t)b * CCH + c) * PIX;
        for (int e = tid; e < 62 * 110; e += 160) {
            const int tr = e / 110, tc = e % 110;
            const int gr = row0 - 15 + tr;
            tile[tr][tc] = (gr >= 0 && gr < HH) ? xp[gr * HH + tc] : 0.f;
        }
        __syncthreads();

        if (active) {
#pragma unroll
            for (int u = 0; u < 7; u++) {
                const int trow = r_local + 5 * u;
                float xr[28];
#pragma unroll
                for (int t = 0; t < 28; t++) {
                    const int col = res + 5 * t - 15;
                    xr[t] = (col >= 0 && col < HH) ? tile[trow][col] : 0.f;
                }
#pragma unroll
                for (int v = 0; v < 7; v++) {
                    const float wv = ws[u * 7 + v];
#pragma unroll
                    for (int m = 0; m < 22; m++)
                        acc[m] += wv * xr[m + v];
                }
            }
        }
    }

    if (active) {
        const int orow = row0 + r_local;
#pragma unroll
        for (int m = 0; m < 22; m++) {
            const int col = res + 5 * m;
            g_y[cc][b * PIX + orow * HH + col] = acc[m];
        }
    }
}

// ---------------------------------------------------------------------------
// 2) importance = sigmoid(gelu(BN(conv + bias)))
// ---------------------------------------------------------------------------
__global__ void imp_kernel(const float* __restrict__ cb, const float* __restrict__ bg,
                           const float* __restrict__ bb, const float* __restrict__ bm,
                           const float* __restrict__ bv)
{
    const int i = blockIdx.x * 256 + threadIdx.x;
    if (i >= BATCH * PIX) return;
    float y = g_y[0][i] + g_y[1][i] + g_y[2][i] + g_y[3][i] + cb[0];
    const float scale = bg[0] * rsqrtf(bv[0] + 1e-5f);
    y = (y - bm[0]) * scale + bb[0];
    const float g = 0.5f * y * (1.f + erff(y * 0.70710678118654752f));
    g_imp[i] = 1.f / (1.f + expf(-g));
}

// ---------------------------------------------------------------------------
// 3) top-K per batch: radix-style bit binary search for the K-th largest
//    (values in (0,1) -> positive floats -> uint bits are order-preserving),
//    then ordered selection scan. Ties: lowest index first (matches XLA),
//    output indices naturally ascending (matches jnp.sort).
// ---------------------------------------------------------------------------
__device__ __forceinline__ int block_scan_incl(int x, int tid, int* wsum, int* total)
{
    __syncthreads();                       // protect wsum reuse
    const int lane = tid & 31, w = tid >> 5;
    int v = x;
#pragma unroll
    for (int off = 1; off < 32; off <<= 1) {
        int y = __shfl_up_sync(0xffffffffu, v, off);
        if (lane >= off) v += y;
    }
    if (lane == 31) wsum[w] = v;
    __syncthreads();
    if (w == 0) {
        int s = (lane < 8) ? wsum[lane] : 0;
#pragma unroll
        for (int off = 1; off < 8; off <<= 1) {
            int y = __shfl_up_sync(0xffffffffu, s, off);
            if (lane >= off) s += y;
        }
        if (lane < 8) wsum[lane] = s;
    }
    __syncthreads();
    const int carry = (w > 0) ? wsum[w - 1] : 0;
    *total = wsum[7];
    return v + carry;
}

__global__ void topk_kernel()
{
    const int b   = blockIdx.x;
    const int tid = threadIdx.x;
    const float* v = g_imp + b * PIX;
    __shared__ int red[256];
    __shared__ int wsum[8];

    unsigned prefix = 0;
    for (int bit = 30; bit >= 0; --bit) {
        const unsigned cand = prefix | (1u << bit);
        int cnt = 0;
        for (int i = tid; i < PIX; i += 256)
            cnt += (__float_as_uint(v[i]) >= cand);
        red[tid] = cnt; __syncthreads();
        for (int s = 128; s > 0; s >>= 1) {
            if (tid < s) red[tid] += red[tid + s];
            __syncthreads();
        }
        if (red[0] >= KTOK) prefix = cand;
        __syncthreads();
    }
    const unsigned T = prefix;  // exact K-th largest bits

    int cnt = 0;
    for (int i = tid; i < PIX; i += 256)
        cnt += (__float_as_uint(v[i]) > T);
    red[tid] = cnt; __syncthreads();
    for (int s = 128; s > 0; s >>= 1) {
        if (tid < s) red[tid] += red[tid + s];
        __syncthreads();
    }
    const int ties_needed = KTOK - red[0];
    __syncthreads();

    int sel_carry = 0, eq_carry = 0;
    for (int base = 0; base < PIX; base += 256) {
        const int i = base + tid;
        const bool ok = (i < PIX);
        const unsigned bits = ok ? __float_as_uint(v[i]) : 0u;
        const int is_gt = ok && (bits > T);
        const int is_eq = ok && (bits == T);

        int eq_total;
        const int eq_incl = block_scan_incl(is_eq, tid, wsum, &eq_total);
        const int eq_excl = eq_incl - is_eq;
        const int sel = is_gt || (is_eq && (eq_carry + eq_excl) < ties_needed);

        int sel_total;
        const int sel_incl = block_scan_incl(sel, tid, wsum, &sel_total);
        if (sel) g_idx[b * KTOK + sel_carry + sel_incl - 1] = i;
        eq_carry  += eq_total;
        sel_carry += sel_total;
    }
}

// ---------------------------------------------------------------------------
// 4) positional-encoding frequency table (high-precision, matches numpy)
// ---------------------------------------------------------------------------
__global__ void freq_kernel()
{
    const int i = threadIdx.x;           // 64
    const float cst = (float)(-(log(10000.0) / 128.0));
    const float a = (float)(2 * i) * cst;
    g_freq[i] = (float)exp((double)a);
}

// ---------------------------------------------------------------------------
// 5) gather tokens: tokens[b,k,c] = x[b,c,p]*imp[b,p] + PE[p,c]
// ---------------------------------------------------------------------------
__global__ void gather_kernel(const float* __restrict__ x)
{
    const int b = blockIdx.y, k = blockIdx.x, c = threadIdx.x;
    const int p = g_idx[b * KTOK + k];
    const float val = x[((size_t)b * CCH + c) * PIX + p] * g_imp[b * PIX + p];
    const float arg = (float)p * g_freq[c >> 1];
    const float pe  = (c & 1) ? cosf(arg) : sinf(arg);
    g_tokens[((size_t)b * KTOK + k) * CCH + c] = val + pe;
}

// ---------------------------------------------------------------------------
// 6) tiled SGEMM: C[m,n] = act( sum_k A[m,k]*B[n,k] + bias[n] )
//    BM=BN=64, BK=16, 256 threads, 4x4 microtile. All dims divide exactly.
// ---------------------------------------------------------------------------
template <bool RELU>
__global__ void gemm_abt(const float* __restrict__ A, const float* __restrict__ B,
                         const float* __restrict__ bias, float* __restrict__ C,
                         int M, int N, int K)
{
    __shared__ float As[16][68];
    __shared__ float Bs[16][68];

    const int tid = threadIdx.x;
    const int bm = blockIdx.y * 64, bn = blockIdx.x * 64;
    const int tx = tid & 15, ty = tid >> 4;

    float acc[4][4];
#pragma unroll
    for (int i = 0; i < 4; i++)
#pragma unroll
        for (int j = 0; j < 4; j++) acc[i][j] = 0.f;

    for (int k0 = 0; k0 < K; k0 += 16) {
#pragma unroll
        for (int i = 0; i < 4; i++) {
            const int e = tid + i * 256;
            const int m = e >> 4, kk = e & 15;
            As[kk][m] = A[(size_t)(bm + m) * K + k0 + kk];
            Bs[kk][m] = B[(size_t)(bn + m) * K + k0 + kk];
        }
        __syncthreads();
#pragma unroll
        for (int kk = 0; kk < 16; kk++) {
            const float4 a  = *(const float4*)&As[kk][ty * 4];
            const float4 bv = *(const float4*)&Bs[kk][tx * 4];
            acc[0][0] += a.x * bv.x; acc[0][1] += a.x * bv.y; acc[0][2] += a.x * bv.z; acc[0][3] += a.x * bv.w;
            acc[1][0] += a.y * bv.x; acc[1][1] += a.y * bv.y; acc[1][2] += a.y * bv.z; acc[1][3] += a.y * bv.w;
            acc[2][0] += a.z * bv.x; acc[2][1] += a.z * bv.y; acc[2][2] += a.z * bv.z; acc[2][3] += a.z * bv.w;
            acc[3][0] += a.w * bv.x; acc[3][1] += a.w * bv.y; acc[3][2] += a.w * bv.z; acc[3][3] += a.w * bv.w;
        }
        __syncthreads();
    }

    const float4 b4 = *(const float4*)&bias[bn + tx * 4];
#pragma unroll
    for (int i = 0; i < 4; i++) {
        float4 r;
        r.x = acc[i][0] + b4.x; r.y = acc[i][1] + b4.y;
        r.z = acc[i][2] + b4.z; r.w = acc[i][3] + b4.w;
        if (RELU) {
            r.x = fmaxf(r.x, 0.f); r.y = fmaxf(r.y, 0.f);
            r.z = fmaxf(r.z, 0.f); r.w = fmaxf(r.w, 0.f);
        }
        *(float4*)&C[(size_t)(bm + ty * 4 + i) * N + bn + tx * 4] = r;
    }
}

// ---------------------------------------------------------------------------
// 7) fused attention: one block per (head, batch). K/V tiles resident in smem,
//    online softmax with chunk-8 deferred rescale. hd=16, 768 keys.
// ---------------------------------------------------------------------------
__global__ void attn_kernel()
{
    extern __shared__ float sm[];
    float* Ks = sm;                 // [768][16]
    float* Vs = sm + KTOK * HD;     // [768][16]

    const int h = blockIdx.x, b = blockIdx.y;
    const int tid = threadIdx.x;
    const float* qkv = g_qkv + (size_t)b * KTOK * 3 * CCH;

    for (int e = tid; e < KTOK * HD; e += 256) {
        const int j = e >> 4, d = e & 15;
        Ks[e] = qkv[(size_t)j * 384 + 128 + h * HD + d];
        Vs[e] = qkv[(size_t)j * 384 + 256 + h * HD + d];
    }
    __syncthreads();

    for (int qi = 0; qi < 3; qi++) {
        const int q = qi * 256 + tid;
        const float4* qp = (const float4*)(qkv + (size_t)q * 384 + h * HD);
        float4 q0 = qp[0], q1 = qp[1], q2 = qp[2], q3 = qp[3];
        const float sc0 = 0.25f;   // 1/sqrt(16)
        q0.x *= sc0; q0.y *= sc0; q0.z *= sc0; q0.w *= sc0;
        q1.x *= sc0; q1.y *= sc0; q1.z *= sc0; q1.w *= sc0;
        q2.x *= sc0; q2.y *= sc0; q2.z *= sc0; q2.w *= sc0;
        q3.x *= sc0; q3.y *= sc0; q3.z *= sc0; q3.w *= sc0;

        float m = -1e30f, l = 0.f;
        float4 a0 = {0,0,0,0}, a1 = {0,0,0,0}, a2 = {0,0,0,0}, a3 = {0,0,0,0};

        for (int j0 = 0; j0 < KTOK; j0 += 8) {
            float s[8];
#pragma unroll
            for (int jj = 0; jj < 8; jj++) {
                const float4* kp = (const float4*)(Ks + (size_t)(j0 + jj) * HD);
                const float4 k0 = kp[0], k1 = kp[1], k2 = kp[2], k3 = kp[3];
                s[jj] = q0.x*k0.x + q0.y*k0.y + q0.z*k0.z + q0.w*k0.w
                      + q1.x*k1.x + q1.y*k1.y + q1.z*k1.z + q1.w*k1.w
                      + q2.x*k2.x + q2.y*k2.y + q2.z*k2.z + q2.w*k2.w
                      + q3.x*k3.x + q3.y*k3.y + q3.z*k3.z + q3.w*k3.w;
            }
            float cm = s[0];
#pragma unroll
            for (int jj = 1; jj < 8; jj++) cm = fmaxf(cm, s[jj]);
            const float nm = fmaxf(m, cm);
            const float scale = __expf(m - nm);
            l *= scale;
            a0.x *= scale; a0.y *= scale; a0.z *= scale; a0.w *= scale;
            a1.x *= scale; a1.y *= scale; a1.z *= scale; a1.w *= scale;
            a2.x *= scale; a2.y *= scale; a2.z *= scale; a2.w *= scale;
            a3.x *= scale; a3.y *= scale; a3.z *= scale; a3.w *= scale;
            m = nm;
#pragma unroll
            for (int jj = 0; jj < 8; jj++) {
                const float e = __expf(s[jj] - m);
                l += e;
                const float4* vp = (const float4*)(Vs + (size_t)(j0 + jj) * HD);
                const float4 v0 = vp[0], v1 = vp[1], v2 = vp[2], v3 = vp[3];
                a0.x += e*v0.x; a0.y += e*v0.y; a0.z += e*v0.z; a0.w += e*v0.w;
                a1.x += e*v1.x; a1.y += e*v1.y; a1.z += e*v1.z; a1.w += e*v1.w;
                a2.x += e*v2.x; a2.y += e*v2.y; a2.z += e*v2.z; a2.w += e*v2.w;
                a3.x += e*v3.x; a3.y += e*v3.y; a3.z += e*v3.z; a3.w += e*v3.w;
            }
        }
        const float inv = 1.f / l;
        float4* op = (float4*)(g_attn + ((size_t)b * KTOK + q) * CCH + h * HD);
        float4 o0 = {a0.x*inv, a0.y*inv, a0.z*inv, a0.w*inv};
        float4 o1 = {a1.x*inv, a1.y*inv, a1.z*inv, a1.w*inv};
        float4 o2 = {a2.x*inv, a2.y*inv, a2.z*inv, a2.w*inv};
        float4 o3 = {a3.x*inv, a3.y*inv, a3.z*inv, a3.w*inv};
        op[0] = o0; op[1] = o1; op[2] = o2; op[3] = o3;
    }
}

// ---------------------------------------------------------------------------
// 8) residual + LayerNorm: out = LN(a + r) * g + b.  One warp per 128-row.
// ---------------------------------------------------------------------------
__global__ void ln_kernel(const float* __restrict__ a, const float* __restrict__ r,
                          const float* __restrict__ g, const float* __restrict__ be,
                          float* __restrict__ out)
{
    const int row  = blockIdx.x * 8 + (threadIdx.x >> 5);
    const int lane = threadIdx.x & 31;
    const float4 va = ((const float4*)(a + (size_t)row * CCH))[lane];
    const float4 vr = ((const float4*)(r + (size_t)row * CCH))[lane];
    float4 t;
    t.x = va.x + vr.x; t.y = va.y + vr.y; t.z = va.z + vr.z; t.w = va.w + vr.w;
    float s  = t.x + t.y + t.z + t.w;
    float s2 = t.x*t.x + t.y*t.y + t.z*t.z + t.w*t.w;
#pragma unroll
    for (int o = 16; o > 0; o >>= 1) {
        s  += __shfl_xor_sync(0xffffffffu, s,  o);
        s2 += __shfl_xor_sync(0xffffffffu, s2, o);
    }
    const float mu  = s * (1.f / 128.f);
    const float var = s2 * (1.f / 128.f) - mu * mu;
    const float inv = rsqrtf(var + 1e-5f);
    const float4 gv = ((const float4*)g)[lane];
    const float4 bv = ((const float4*)be)[lane];
    float4 o;
    o.x = (t.x - mu) * inv * gv.x + bv.x;
    o.y = (t.y - mu) * inv * gv.y + bv.y;
    o.z = (t.z - mu) * inv * gv.z + bv.z;
    o.w = (t.w - mu) * inv * gv.w + bv.w;
    ((float4*)(out + (size_t)row * CCH))[lane] = o;
}

// ---------------------------------------------------------------------------
// 9) out = x * imp (everywhere), then scatter t2 at selected pixels
// ---------------------------------------------------------------------------
__global__ void xs_kernel(const float* __restrict__ x, float* __restrict__ out)
{
    const unsigned i = blockIdx.x * 256u + threadIdx.x;      // float4 groups
    const unsigned total = (unsigned)BATCH * CCH * (PIX / 4);
    if (i >= total) return;
    const unsigned base = i * 4u;
    const unsigned p4 = base % PIX;
    const unsigned b  = (base / PIX) / CCH;
    const float4 xv = *(const float4*)(x + base);
    const float* ip = g_imp + (size_t)b * PIX + p4;
    float4 o;
    o.x = xv.x * ip[0]; o.y = xv.y * ip[1]; o.z = xv.z * ip[2]; o.w = xv.w * ip[3];
    *(float4*)(out + base) = o;
}

__global__ void scatter_kernel(float* __restrict__ out)
{
    const int b = blockIdx.y, k = blockIdx.x, c = threadIdx.x;
    const int p = g_idx[b * KTOK + k];
    out[((size_t)b * CCH + c) * PIX + p] = g_t2[((size_t)b * KTOK + k) * CCH + c];
}

// ---------------------------------------------------------------------------
// launch
// ---------------------------------------------------------------------------
extern "C" void kernel_launch(void* const* d_in, const int* in_sizes, int n_in,
                              void* d_out, int out_size)
{
    const float* x      = (const float*)d_in[0];
    const float* conv_w = (const float*)d_in[1];
    const float* conv_b = (const float*)d_in[2];
    const float* bn_g   = (const float*)d_in[3];
    const float* bn_b   = (const float*)d_in[4];
    const float* bn_m   = (const float*)d_in[5];
    const float* bn_v   = (const float*)d_in[6];
    const float* w_qkv  = (const float*)d_in[7];
    const float* b_qkv  = (const float*)d_in[8];
    const float* w_o    = (const float*)d_in[9];
    const float* b_o    = (const float*)d_in[10];
    const float* ln1_g  = (const float*)d_in[11];
    const float* ln1_b  = (const float*)d_in[12];
    const float* w1     = (const float*)d_in[13];
    const float* b1     = (const float*)d_in[14];
    const float* w2     = (const float*)d_in[15];
    const float* b2     = (const float*)d_in[16];
    const float* ln2_g  = (const float*)d_in[17];
    const float* ln2_b  = (const float*)d_in[18];
    float* out = (float*)d_out;

    // device-global scratch addresses for pointer-arg kernels
    float *p_tokens, *p_qkv, *p_attn, *p_t1, *p_h1, *p_tmp, *p_t2;
    cudaGetSymbolAddress((void**)&p_tokens, g_tokens);
    cudaGetSymbolAddress((void**)&p_qkv,    g_qkv);
    cudaGetSymbolAddress((void**)&p_attn,   g_attn);
    cudaGetSymbolAddress((void**)&p_t1,     g_t1);
    cudaGetSymbolAddress((void**)&p_h1,     g_h1);
    cudaGetSymbolAddress((void**)&p_tmp,    g_tmp);
    cudaGetSymbolAddress((void**)&p_t2,     g_t2);

    // conv -> importance -> top-K -> tokens
    freq_kernel<<<1, 64>>>();
    conv_kernel<<<dim3(4, 4, BATCH), 160>>>(x, conv_w);
    imp_kernel<<<(BATCH * PIX + 255) / 256, 256>>>(conv_b, bn_g, bn_b, bn_m, bn_v);
    topk_kernel<<<BATCH, 256>>>();
    gather_kernel<<<dim3(KTOK, BATCH), CCH>>>(x);

    // transformer encoder layer
    gemm_abt<false><<<dim3(384 / 64, NTOK / 64), 256>>>(p_tokens, w_qkv, b_qkv, p_qkv, NTOK, 384, 128);

    cudaFuncSetAttribute(attn_kernel, cudaFuncAttributeMaxDynamicSharedMemorySize,
                         2 * KTOK * HD * (int)sizeof(float));
    attn_kernel<<<dim3(NHEAD, BATCH), 256, 2 * KTOK * HD * sizeof(float)>>>();

    gemm_abt<false><<<dim3(128 / 64, NTOK / 64), 256>>>(p_attn, w_o, b_o, p_tmp, NTOK, 128, 128);
    ln_kernel<<<NTOK / 8, 256>>>(p_tokens, p_tmp, ln1_g, ln1_b, p_t1);
    gemm_abt<true ><<<dim3(256 / 64, NTOK / 64), 256>>>(p_t1, w1, b1, p_h1, NTOK, 256, 128);
    gemm_abt<false><<<dim3(128 / 64, NTOK / 64), 256>>>(p_h1, w2, b2, p_tmp, NTOK, 128, 256);
    ln_kernel<<<NTOK / 8, 256>>>(p_t1, p_tmp, ln2_g, ln2_b, p_t2);

    // assemble output
    xs_kernel<<<(BATCH * CCH * (PIX / 4) + 255) / 256, 256>>>(x, out);
    scatter_kernel<<<dim3(KTOK, BATCH), CCH>>>(out);
}

// round 2
// speedup vs baseline: 1.0325x; 1.0325x over previous
#include <cuda_runtime.h>
#include <cuda_bf16.h>
#include <math.h>

// ---------------------------------------------------------------------------
// Problem constants
// ---------------------------------------------------------------------------
#define BATCH 32
#define CCH   128           // channels / d_model
#define HH    110           // spatial
#define PIX   (HH*HH)       // 12100
#define KTOK  768
#define NHEAD 8
#define HD    16
#define NTOK  (BATCH*KTOK)  // 24576

typedef unsigned long long u64;

// ---------------------------------------------------------------------------
// packed fp32x2 helpers (Blackwell FFMA2 path — only reachable via PTX)
// ---------------------------------------------------------------------------
__device__ __forceinline__ void ffma2(u64 &d, u64 a, u64 b) {
    asm("fma.rn.f32x2 %0, %1, %2, %0;" : "+l"(d) : "l"(a), "l"(b));
}
__device__ __forceinline__ u64 fmul2(u64 a, u64 b) {
    u64 d; asm("mul.rn.f32x2 %0, %1, %2;" : "=l"(d) : "l"(a), "l"(b)); return d;
}
__device__ __forceinline__ u64 fadd2(u64 a, u64 b) {
    u64 d; asm("add.rn.f32x2 %0, %1, %2;" : "=l"(d) : "l"(a), "l"(b)); return d;
}
__device__ __forceinline__ u64 dup2(float x) {
    u64 d; asm("mov.b64 %0, {%1, %1};" : "=l"(d) : "f"(x)); return d;
}
__device__ __forceinline__ u64 pack2(float x, float y) {
    u64 d; asm("mov.b64 %0, {%1, %2};" : "=l"(d) : "f"(x), "f"(y)); return d;
}
__device__ __forceinline__ float2 unpack2(u64 v) {
    float2 r; asm("mov.b64 {%0, %1}, %2;" : "=f"(r.x), "=f"(r.y) : "l"(v)); return r;
}

// ---------------------------------------------------------------------------
// Scratch (static device globals; no allocation allowed)
// ---------------------------------------------------------------------------
__device__ float g_y[4][BATCH*PIX];          // conv partial sums (4 channel chunks)
__device__ float g_imp[BATCH*PIX];           // importance map
__device__ int   g_idx[BATCH*KTOK];          // selected (sorted) pixel indices
__device__ float g_freq[64];                 // positional-encoding frequencies
__device__ float g_tokens[NTOK*CCH];
__device__ float g_qkv[NTOK*3*CCH];
__device__ float g_attn[NTOK*CCH];
__device__ float g_t1[NTOK*CCH];
__device__ float g_h1[NTOK*2*CCH];
__device__ float g_tmp[NTOK*CCH];
__device__ float g_t2[NTOK*CCH];

// ---------------------------------------------------------------------------
// 1) Dilated conv (k=7, d=5, p=15), residue decomposition + f32x2 packing.
//    grid (4 cchunk, 4 rowchunk, 32 batch), block 160 (= 32 rows x 5 residues)
//    Each thread: one output row + one column residue -> 22 outputs (11 pairs).
//    Tile padded by 15 columns each side so all taps are unconditional.
// ---------------------------------------------------------------------------
__global__ void conv_kernel(const float* __restrict__ x, const float* __restrict__ w)
{
    __shared__ float tile[62][140];
    __shared__ float ws[49];

    const int cc  = blockIdx.x;
    const int rc  = blockIdx.y;
    const int b   = blockIdx.z;
    const int tid = threadIdx.x;

    const int r_local = tid / 5;
    const int res     = tid % 5;
    const int row0    = rc * 32;
    const int nrows   = min(32, HH - row0);
    const bool active = (r_local < nrows);

    // zero full tile once (borders stay zero for the whole channel loop)
    for (int e = tid; e < 62 * 140; e += 160)
        ((float*)tile)[e] = 0.f;

    u64 acc[11];
#pragma unroll
    for (int p = 0; p < 11; p++) acc[p] = 0ull;

    for (int ci = 0; ci < 32; ci++) {
        const int c = cc * 32 + ci;
        __syncthreads();
        if (tid < 49) ws[tid] = w[c * 49 + tid];
        const float* xp = x + ((size_t)b * CCH + c) * PIX;
        for (int e = tid; e < 62 * 110; e += 160) {
            const int tr = e / 110, tc = e % 110;
            const int gr = row0 - 15 + tr;
            tile[tr][15 + tc] = (gr >= 0 && gr < HH) ? xp[gr * HH + tc] : 0.f;
        }
        __syncthreads();

        if (active) {
#pragma unroll
            for (int u = 0; u < 7; u++) {
                const int trow = r_local + 5 * u;
                // build packed sliding pairs xp2[t] = {x[t], x[t+1]}, taps at res+5t
                u64 xp2[27];
                float prev = tile[trow][res];
#pragma unroll
                for (int t = 0; t < 27; t++) {
                    const float cur = tile[trow][res + 5 * (t + 1)];
                    xp2[t] = pack2(prev, cur);
                    prev = cur;
                }
#pragma unroll
                for (int v = 0; v < 7; v++) {
                    const u64 wd = dup2(ws[u * 7 + v]);
#pragma unroll
                    for (int p = 0; p < 11; p++)
                        ffma2(acc[p], wd, xp2[2 * p + v]);
                }
            }
        }
    }

    if (active) {
        const int orow = row0 + r_local;
#pragma unroll
        for (int p = 0; p < 11; p++) {
            const float2 t = unpack2(acc[p]);
            g_y[cc][b * PIX + orow * HH + res + 5 * (2 * p)]     = t.x;
            g_y[cc][b * PIX + orow * HH + res + 5 * (2 * p + 1)] = t.y;
        }
    }
}

// ---------------------------------------------------------------------------
// 2) importance = sigmoid(gelu(BN(conv + bias)))
// ---------------------------------------------------------------------------
__global__ void imp_kernel(const float* __restrict__ cb, const float* __restrict__ bg,
                           const float* __restrict__ bb, const float* __restrict__ bm,
                           const float* __restrict__ bv)
{
    const int i = blockIdx.x * 256 + threadIdx.x;
    if (i >= BATCH * PIX) return;
    float y = g_y[0][i] + g_y[1][i] + g_y[2][i] + g_y[3][i] + cb[0];
    const float scale = bg[0] * rsqrtf(bv[0] + 1e-5f);
    y = (y - bm[0]) * scale + bb[0];
    const float g = 0.5f * y * (1.f + erff(y * 0.70710678118654752f));
    g_imp[i] = 1.f / (1.f + expf(-g));
}

// ---------------------------------------------------------------------------
// 3) top-K per batch: 4-round radix-256 threshold search + ordered selection.
//    Values in (0,1) -> positive floats -> uint bits order-preserving.
//    Ties: lowest index first (matches XLA), output ascending (matches sort).
// ---------------------------------------------------------------------------
__device__ __forceinline__ int block_scan_incl(int x, int tid, int* wsum, int* total)
{
    __syncthreads();
    const int lane = tid & 31, w = tid >> 5;
    int v = x;
#pragma unroll
    for (int off = 1; off < 32; off <<= 1) {
        int y = __shfl_up_sync(0xffffffffu, v, off);
        if (lane >= off) v += y;
    }
    if (lane == 31) wsum[w] = v;
    __syncthreads();
    if (w == 0) {
        int s = (lane < 8) ? wsum[lane] : 0;
#pragma unroll
        for (int off = 1; off < 8; off <<= 1) {
            int y = __shfl_up_sync(0xffffffffu, s, off);
            if (lane >= off) s += y;
        }
        if (lane < 8) wsum[lane] = s;
    }
    __syncthreads();
    const int carry = (w > 0) ? wsum[w - 1] : 0;
    *total = wsum[7];
    return v + carry;
}

__global__ void topk_kernel()
{
    const int b   = blockIdx.x;
    const int tid = threadIdx.x;
    const float* v = g_imp + b * PIX;
    __shared__ int hist[256];
    __shared__ unsigned sh_prefix;
    __shared__ int sh_above;
    __shared__ int wsum[8];

    unsigned prefix = 0;
    int kneed = KTOK;

#pragma unroll
    for (int shift = 24; shift >= 0; shift -= 8) {
        hist[tid] = 0;
        __syncthreads();
        const unsigned pm = (shift == 24) ? 0u : (0xFFFFFFFFu << (shift + 8));
        for (int i = tid; i < PIX; i += 256) {
            const unsigned bits = __float_as_uint(v[i]);
            if ((bits & pm) == prefix)
                atomicAdd(&hist[(bits >> shift) & 255], 1);
        }
        __syncthreads();
        // suffix sums: hist[t] = count(byte >= t)
        for (int off = 1; off < 256; off <<= 1) {
            const int val = (tid + off < 256) ? hist[tid + off] : 0;
            __syncthreads();
            hist[tid] += val;
            __syncthreads();
        }
        const int here  = hist[tid];
        const int above = (tid == 255) ? 0 : hist[tid + 1];
        if (here >= kneed && above < kneed) {
            sh_prefix = prefix | ((unsigned)tid << shift);
            sh_above  = above;
        }
        __syncthreads();
        prefix = sh_prefix;
        kneed -= sh_above;
        __syncthreads();
    }

    const unsigned T = prefix;        // exact bits of K-th largest
    const int ties_needed = kneed;    // how many ==T to take (lowest idx first)

    int sel_carry = 0, eq_carry = 0;
    for (int base = 0; base < PIX; base += 256) {
        const int i = base + tid;
        const bool ok = (i < PIX);
        const unsigned bits = ok ? __float_as_uint(v[i]) : 0u;
        const int is_gt = ok && (bits > T);
        const int is_eq = ok && (bits == T);

        int eq_total;
        const int eq_incl = block_scan_incl(is_eq, tid, wsum, &eq_total);
        const int eq_excl = eq_incl - is_eq;
        const int sel = is_gt || (is_eq && (eq_carry + eq_excl) < ties_needed);

        int sel_total;
        const int sel_incl = block_scan_incl(sel, tid, wsum, &sel_total);
        if (sel) g_idx[b * KTOK + sel_carry + sel_incl - 1] = i;
        eq_carry  += eq_total;
        sel_carry += sel_total;
    }
}

// ---------------------------------------------------------------------------
// 4) positional-encoding frequency table (high-precision, matches numpy)
// ---------------------------------------------------------------------------
__global__ void freq_kernel()
{
    const int i = threadIdx.x;           // 64
    const float cst = (float)(-(log(10000.0) / 128.0));
    const float a = (float)(2 * i) * cst;
    g_freq[i] = (float)exp((double)a);
}

// ---------------------------------------------------------------------------
// 5) gather tokens: tokens[b,k,c] = x[b,c,p]*imp[b,p] + PE[p,c]
// ---------------------------------------------------------------------------
__global__ void gather_kernel(const float* __restrict__ x)
{
    const int b = blockIdx.y, k = blockIdx.x, c = threadIdx.x;
    const int p = g_idx[b * KTOK + k];
    const float val = x[((size_t)b * CCH + c) * PIX + p] * g_imp[b * PIX + p];
    const float arg = (float)p * g_freq[c >> 1];
    const float pe  = (c & 1) ? cosf(arg) : sinf(arg);
    g_tokens[((size_t)b * KTOK + k) * CCH + c] = val + pe;
}

// ---------------------------------------------------------------------------
// 6) tiled SGEMM with FFMA2: C[m,n] = act( sum_k A[m,k]*B[n,k] + bias[n] )
//    BM=BN=128, BK=16, 256 threads, 8x8 microtile packed along N.
// ---------------------------------------------------------------------------
template <bool RELU>
__global__ __launch_bounds__(256) void gemm_abt(
    const float* __restrict__ A, const float* __restrict__ B,
    const float* __restrict__ bias, float* __restrict__ C,
    int M, int N, int K)
{
    __shared__ float As[16][132];
    __shared__ float Bs[16][132];

    const int tid = threadIdx.x;
    const int bm = blockIdx.y * 128, bn = blockIdx.x * 128;
    const int tx = tid & 15, ty = tid >> 4;

    u64 acc[8][4];
#pragma unroll
    for (int i = 0; i < 8; i++)
#pragma unroll
        for (int j = 0; j < 4; j++) acc[i][j] = 0ull;

    for (int k0 = 0; k0 < K; k0 += 16) {
#pragma unroll
        for (int i = 0; i < 2; i++) {
            const int f  = tid + i * 256;        // 0..511 float4 slots
            const int m  = f >> 2;
            const int kk = (f & 3) * 4;
            const float4 a4 = *(const float4*)&A[(size_t)(bm + m) * K + k0 + kk];
            const float4 b4 = *(const float4*)&B[(size_t)(bn + m) * K + k0 + kk];
            As[kk + 0][m] = a4.x; As[kk + 1][m] = a4.y;
            As[kk + 2][m] = a4.z; As[kk + 3][m] = a4.w;
            Bs[kk + 0][m] = b4.x; Bs[kk + 1][m] = b4.y;
            Bs[kk + 2][m] = b4.z; Bs[kk + 3][m] = b4.w;
        }
        __syncthreads();
#pragma unroll
        for (int kk = 0; kk < 16; kk++) {
            const float4 a0 = *(const float4*)&As[kk][ty * 8];
            const float4 a1 = *(const float4*)&As[kk][ty * 8 + 4];
            const ulonglong2 bl0 = *(const ulonglong2*)&Bs[kk][tx * 8];
            const ulonglong2 bl1 = *(const ulonglong2*)&Bs[kk][tx * 8 + 4];
            const u64 bb[4] = { bl0.x, bl0.y, bl1.x, bl1.y };
            const u64 ad[8] = { dup2(a0.x), dup2(a0.y), dup2(a0.z), dup2(a0.w),
                                dup2(a1.x), dup2(a1.y), dup2(a1.z), dup2(a1.w) };
#pragma unroll
            for (int i = 0; i < 8; i++)
#pragma unroll
                for (int j = 0; j < 4; j++)
                    ffma2(acc[i][j], ad[i], bb[j]);
        }
        __syncthreads();
    }

    const u64* bp = (const u64*)&bias[bn + tx * 8];
    const u64 bb[4] = { bp[0], bp[1], bp[2], bp[3] };
#pragma unroll
    for (int i = 0; i < 8; i++) {
        u64 r[4];
#pragma unroll
        for (int j = 0; j < 4; j++) {
            r[j] = fadd2(acc[i][j], bb[j]);
            if (RELU) {
                float2 t = unpack2(r[j]);
                t.x = fmaxf(t.x, 0.f); t.y = fmaxf(t.y, 0.f);
                r[j] = pack2(t.x, t.y);
            }
        }
        float* crow = &C[(size_t)(bm + ty * 8 + i) * N + bn + tx * 8];
        *(ulonglong2*)(crow)     = make_ulonglong2(r[0], r[1]);
        *(ulonglong2*)(crow + 4) = make_ulonglong2(r[2], r[3]);
    }
}

// ---------------------------------------------------------------------------
// 7) fused attention with FFMA2: one block per (head, batch). K/V resident
//    in smem as packed pairs, online softmax with chunk-8 deferred rescale.
// ---------------------------------------------------------------------------
__global__ void attn_kernel()
{
    extern __shared__ u64 sm2[];
    u64* Ks = sm2;                  // [768][8] packed pairs
    u64* Vs = sm2 + KTOK * 8;

    const int h = blockIdx.x, b = blockIdx.y;
    const int tid = threadIdx.x;
    const float* qkv = g_qkv + (size_t)b * KTOK * 3 * CCH;

    for (int e = tid; e < KTOK * 8; e += 256) {
        const int j = e >> 3, d2 = e & 7;
        Ks[e] = *(const u64*)&qkv[(size_t)j * 384 + 128 + h * HD + d2 * 2];
        Vs[e] = *(const u64*)&qkv[(size_t)j * 384 + 256 + h * HD + d2 * 2];
    }
    __syncthreads();

    for (int qi = 0; qi < 3; qi++) {
        const int q = qi * 256 + tid;
        const u64* qp = (const u64*)(qkv + (size_t)q * 384 + h * HD);
        const u64 sc = dup2(0.25f);    // 1/sqrt(16)
        u64 qv[8];
#pragma unroll
        for (int d = 0; d < 8; d++) qv[d] = fmul2(qp[d], sc);

        float m = -1e30f, l = 0.f;
        u64 a[8];
#pragma unroll
        for (int d = 0; d < 8; d++) a[d] = 0ull;

        for (int j0 = 0; j0 < KTOK; j0 += 8) {
            float s[8];
#pragma unroll
            for (int jj = 0; jj < 8; jj++) {
                const ulonglong2* kp = (const ulonglong2*)&Ks[(size_t)(j0 + jj) * 8];
                const ulonglong2 k0 = kp[0], k1 = kp[1], k2 = kp[2], k3 = kp[3];
                u64 d2 = fmul2(qv[0], k0.x);
                ffma2(d2, qv[1], k0.y);
                ffma2(d2, qv[2], k1.x);
                ffma2(d2, qv[3], k1.y);
                ffma2(d2, qv[4], k2.x);
                ffma2(d2, qv[5], k2.y);
                ffma2(d2, qv[6], k3.x);
                ffma2(d2, qv[7], k3.y);
                const float2 t = unpack2(d2);
                s[jj] = t.x + t.y;
            }
            float cm = s[0];
#pragma unroll
            for (int jj = 1; jj < 8; jj++) cm = fmaxf(cm, s[jj]);
            const float nm = fmaxf(m, cm);
            const float scale = __expf(m - nm);
            const u64 sc2 = dup2(scale);
            l *= scale;
#pragma unroll
            for (int d = 0; d < 8; d++) a[d] = fmul2(a[d], sc2);
            m = nm;
#pragma unroll
            for (int jj = 0; jj < 8; jj++) {
                const float e = __expf(s[jj] - m);
                l += e;
                const u64 e2 = dup2(e);
                const ulonglong2* vp = (const ulonglong2*)&Vs[(size_t)(j0 + jj) * 8];
                const ulonglong2 v0 = vp[0], v1 = vp[1], v2 = vp[2], v3 = vp[3];
                ffma2(a[0], e2, v0.x);
                ffma2(a[1], e2, v0.y);
                ffma2(a[2], e2, v1.x);
                ffma2(a[3], e2, v1.y);
                ffma2(a[4], e2, v2.x);
                ffma2(a[5], e2, v2.y);
                ffma2(a[6], e2, v3.x);
                ffma2(a[7], e2, v3.y);
            }
        }
        const u64 iv = dup2(1.f / l);
        float* orow = g_attn + ((size_t)b * KTOK + q) * CCH + h * HD;
#pragma unroll
        for (int d = 0; d < 4; d++) {
            const u64 o0 = fmul2(a[2 * d], iv);
            const u64 o1 = fmul2(a[2 * d + 1], iv);
            *(ulonglong2*)(orow + d * 4) = make_ulonglong2(o0, o1);
        }
    }
}

// ---------------------------------------------------------------------------
// 8) residual + LayerNorm: out = LN(a + r) * g + b.  One warp per 128-row.
// ---------------------------------------------------------------------------
__global__ void ln_kernel(const float* __restrict__ a, const float* __restrict__ r,
                          const float* __restrict__ g, const float* __restrict__ be,
                          float* __restrict__ out)
{
    const int row  = blockIdx.x * 8 + (threadIdx.x >> 5);
    const int lane = threadIdx.x & 31;
    const float4 va = ((const float4*)(a + (size_t)row * CCH))[lane];
    const float4 vr = ((const float4*)(r + (size_t)row * CCH))[lane];
    float4 t;
    t.x = va.x + vr.x; t.y = va.y + vr.y; t.z = va.z + vr.z; t.w = va.w + vr.w;
    float s  = t.x + t.y + t.z + t.w;
    float s2 = t.x*t.x + t.y*t.y + t.z*t.z + t.w*t.w;
#pragma unroll
    for (int o = 16; o > 0; o >>= 1) {
        s  += __shfl_xor_sync(0xffffffffu, s,  o);
        s2 += __shfl_xor_sync(0xffffffffu, s2, o);
    }
    const float mu  = s * (1.f / 128.f);
    const float var = s2 * (1.f / 128.f) - mu * mu;
    const float inv = rsqrtf(var + 1e-5f);
    const float4 gv = ((const float4*)g)[lane];
    const float4 bv = ((const float4*)be)[lane];
    float4 o;
    o.x = (t.x - mu) * inv * gv.x + bv.x;
    o.y = (t.y - mu) * inv * gv.y + bv.y;
    o.z = (t.z - mu) * inv * gv.z + bv.z;
    o.w = (t.w - mu) * inv * gv.w + bv.w;
    ((float4*)(out + (size_t)row * CCH))[lane] = o;
}

// ---------------------------------------------------------------------------
// 9) out = x * imp (everywhere), then scatter t2 at selected pixels
// ---------------------------------------------------------------------------
__global__ void xs_kernel(const float* __restrict__ x, float* __restrict__ out)
{
    const unsigned i = blockIdx.x * 256u + threadIdx.x;      // float4 groups
    const unsigned total = (unsigned)BATCH * CCH * (PIX / 4);
    if (i >= total) return;
    const unsigned base = i * 4u;
    const unsigned p4 = base % PIX;
    const unsigned b  = (base / PIX) / CCH;
    const float4 xv = *(const float4*)(x + base);
    const float* ip = g_imp + (size_t)b * PIX + p4;
    float4 o;
    o.x = xv.x * ip[0]; o.y = xv.y * ip[1]; o.z = xv.z * ip[2]; o.w = xv.w * ip[3];
    *(float4*)(out + base) = o;
}

__global__ void scatter_kernel(float* __restrict__ out)
{
    const int b = blockIdx.y, k = blockIdx.x, c = threadIdx.x;
    const int p = g_idx[b * KTOK + k];
    out[((size_t)b * CCH + c) * PIX + p] = g_t2[((size_t)b * KTOK + k) * CCH + c];
}

// ---------------------------------------------------------------------------
// launch
// ---------------------------------------------------------------------------
extern "C" void kernel_launch(void* const* d_in, const int* in_sizes, int n_in,
                              void* d_out, int out_size)
{
    const float* x      = (const float*)d_in[0];
    const float* conv_w = (const float*)d_in[1];
    const float* conv_b = (const float*)d_in[2];
    const float* bn_g   = (const float*)d_in[3];
    const float* bn_b   = (const float*)d_in[4];
    const float* bn_m   = (const float*)d_in[5];
    const float* bn_v   = (const float*)d_in[6];
    const float* w_qkv  = (const float*)d_in[7];
    const float* b_qkv  = (const float*)d_in[8];
    const float* w_o    = (const float*)d_in[9];
    const float* b_o    = (const float*)d_in[10];
    const float* ln1_g  = (const float*)d_in[11];
    const float* ln1_b  = (const float*)d_in[12];
    const float* w1     = (const float*)d_in[13];
    const float* b1     = (const float*)d_in[14];
    const float* w2     = (const float*)d_in[15];
    const float* b2     = (const float*)d_in[16];
    const float* ln2_g  = (const float*)d_in[17];
    const float* ln2_b  = (const float*)d_in[18];
    float* out = (float*)d_out;

    float *p_tokens, *p_qkv, *p_attn, *p_t1, *p_h1, *p_tmp, *p_t2;
    cudaGetSymbolAddress((void**)&p_tokens, g_tokens);
    cudaGetSymbolAddress((void**)&p_qkv,    g_qkv);
    cudaGetSymbolAddress((void**)&p_attn,   g_attn);
    cudaGetSymbolAddress((void**)&p_t1,     g_t1);
    cudaGetSymbolAddress((void**)&p_h1,     g_h1);
    cudaGetSymbolAddress((void**)&p_tmp,    g_tmp);
    cudaGetSymbolAddress((void**)&p_t2,     g_t2);

    // conv -> importance -> top-K -> tokens
    freq_kernel<<<1, 64>>>();
    conv_kernel<<<dim3(4, 4, BATCH), 160>>>(x, conv_w);
    imp_kernel<<<(BATCH * PIX + 255) / 256, 256>>>(conv_b, bn_g, bn_b, bn_m, bn_v);
    topk_kernel<<<BATCH, 256>>>();
    gather_kernel<<<dim3(KTOK, BATCH), CCH>>>(x);

    // transformer encoder layer
    gemm_abt<false><<<dim3(384 / 128, NTOK / 128), 256>>>(p_tokens, w_qkv, b_qkv, p_qkv, NTOK, 384, 128);

    cudaFuncSetAttribute(attn_kernel, cudaFuncAttributeMaxDynamicSharedMemorySize,
                         2 * KTOK * HD * (int)sizeof(float));
    attn_kernel<<<dim3(NHEAD, BATCH), 256, 2 * KTOK * HD * sizeof(float)>>>();

    gemm_abt<false><<<dim3(128 / 128, NTOK / 128), 256>>>(p_attn, w_o, b_o, p_tmp, NTOK, 128, 128);
    ln_kernel<<<NTOK / 8, 256>>>(p_tokens, p_tmp, ln1_g, ln1_b, p_t1);
    gemm_abt<true ><<<dim3(256 / 128, NTOK / 128), 256>>>(p_t1, w1, b1, p_h1, NTOK, 256, 128);
    gemm_abt<false><<<dim3(128 / 128, NTOK / 128), 256>>>(p_h1, w2, b2, p_tmp, NTOK, 128, 256);
    ln_kernel<<<NTOK / 8, 256>>>(p_t1, p_tmp, ln2_g, ln2_b, p_t2);

    // assemble output
    xs_kernel<<<(BATCH * CCH * (PIX / 4) + 255) / 256, 256>>>(x, out);
    scatter_kernel<<<dim3(KTOK, BATCH), CCH>>>(out);
}